// round 10
// baseline (speedup 1.0000x reference)
#include <cuda_runtime.h>

// DihedralToCartesian R10: R9 structure (best measured) + vectorized I/O.
//  - phase 0 loads sin/cos as float2 (8B-aligned by construction)
//  - phase 4 flat copy as float4 (buf/gout layouts identical, 16B-aligned)
// Math identical to R9: r1/r2 precomputed in parallel; analytic 1/sin(alpha)
// n-scale (safe: w re-normalized every step); one rsqrt on the serial chain.

#define TPB    96
#define NRES   126
#define CHAINS 16
#define SEG    6
#define LSEG   21             // 21 % 3 == 0 -> canonical entry frame valid

__device__ __forceinline__ float frsqrt(float x) {
    float y;
    asm("rsqrt.approx.f32 %0, %1;" : "=f"(y) : "f"(x));
    return y;
}

__global__ void __launch_bounds__(TPB, 7)
dihedral_kernel(const float* __restrict__ angles,
                const float* __restrict__ prev,
                float* __restrict__ out)
{
    // buf record (3 floats/step): (r1, r2, -) after phase 0 -> local points
    // after phase 1 -> global points after phase 3 (in place).
    __shared__ __align__(16) float buf[CHAINS * NRES * 3];   // 24192 B
    __shared__ float ex [CHAINS * SEG * 9];                  // exit p, w, v
    __shared__ float rp [CHAINS * SEG * 12];                 // R cols + p

    const int tid   = threadIdx.x;
    const int c     = tid / SEG;
    const int s     = tid - c * SEG;
    const int Bbase = blockIdx.x * CHAINS;

    const float CA0 = cosf(2.028f), SA0 = sinf(2.028f), B0 = 1.329f;
    const float CA1 = cosf(2.124f), SA1 = sinf(2.124f), B1 = 1.458f;
    const float CA2 = cosf(1.941f), SA2 = sinf(1.941f), B2 = 1.523f;
    const float IS0 = 1.0f / SA0, IS1 = 1.0f / SA1, IS2 = 1.0f / SA2;

    // ---- phase 0: vectorized load + angle normalization (parallel) ----
    // 2016 records per CTA = 1008 float2-pairs; thread handles pair p.
    const float* gang = angles + (size_t)Bbase * (2 * NRES);
    #define PAIR(p) do {                                                        \
        int cc = (p) / (NRES / 2);                                              \
        int pj = (p) - cc * (NRES / 2);                                         \
        int j0 = pj * 2;                                                        \
        float2 s2 = *(const float2*)(gang + cc * (2 * NRES) + j0);              \
        float2 c2 = *(const float2*)(gang + cc * (2 * NRES) + NRES + j0);       \
        int k0 = j0 % 3;                                                        \
        float sa0 = (k0 == 0) ? SA0 : (k0 == 1) ? SA1 : SA2;                    \
        float sa1 = (k0 == 0) ? SA1 : (k0 == 1) ? SA2 : SA0;                    \
        float t0 = sa0 * frsqrt(fmaf(s2.x, s2.x, fmaf(c2.x, c2.x, 1e-8f)));     \
        float t1 = sa1 * frsqrt(fmaf(s2.y, s2.y, fmaf(c2.y, c2.y, 1e-8f)));     \
        int e0 = (cc * NRES + j0) * 3;                                          \
        buf[e0 + 0] =  t0 * c2.x;                                               \
        buf[e0 + 1] = -t0 * s2.x;                                               \
        buf[e0 + 3] =  t1 * c2.y;                                               \
        buf[e0 + 4] = -t1 * s2.y;                                               \
    } while (0)
    #pragma unroll
    for (int i = 0; i < 10; ++i)
        PAIR(tid + i * TPB);
    if (tid < 48)
        PAIR(tid + 960);
    #undef PAIR
    __syncthreads();

    // ---- phase 1: LSEG serial steps per segment ----
    float* rec = &buf[(c * NRES + s * LSEG) * 3];
    float px, py, pz, vx, vy, vz, wx, wy, wz;

    #define STEP(j, CAk, Bk, ISk) do {                                          \
        float r1 = rec[(j) * 3 + 0], r2 = rec[(j) * 3 + 1];                     \
        float nx = (wy * vz - wz * vy) * (ISk);                                 \
        float ny = (wz * vx - wx * vz) * (ISk);                                 \
        float nz = (wx * vy - wy * vx) * (ISk);                                 \
        float mx = wy * nz - wz * ny;                                           \
        float my = wz * nx - wx * nz;                                           \
        float mz = wx * ny - wy * nx;                                           \
        float ux = fmaf(-(CAk), wx, fmaf(r1, mx, r2 * nx));                     \
        float uy = fmaf(-(CAk), wy, fmaf(r1, my, r2 * ny));                     \
        float uz = fmaf(-(CAk), wz, fmaf(r1, mz, r2 * nz));                     \
        px = fmaf((Bk), ux, px);                                                \
        py = fmaf((Bk), uy, py);                                                \
        pz = fmaf((Bk), uz, pz);                                                \
        rec[(j) * 3 + 0] = px;                                                  \
        rec[(j) * 3 + 1] = py;                                                  \
        rec[(j) * 3 + 2] = pz;                                                  \
        float iun = frsqrt(fmaf(ux, ux, fmaf(uy, uy, uz * uz)));                \
        vx = wx; vy = wy; vz = wz;                                              \
        wx = ux * iun; wy = uy * iun; wz = uz * iun;                            \
    } while (0)

    if (s == 0) {
        // real geometry from prev_three; reference-faithful first step
        const float* pp = prev + (size_t)(Bbase + c) * 9;
        float ax = pp[0], ay = pp[1], az = pp[2];
        float bx = pp[3], by = pp[4], bz = pp[5];
        px = pp[6]; py = pp[7]; pz = pp[8];

        float r1 = rec[0], r2 = rec[1];

        float bcx = (bx - px) + 1e-8f;
        float bcy = (by - py) + 1e-8f;
        float bcz = (bz - pz) + 1e-8f;
        float ib = frsqrt(fmaf(bcx, bcx, fmaf(bcy, bcy, bcz * bcz)));
        bcx *= ib; bcy *= ib; bcz *= ib;

        float qx = bx - ax, qy = by - ay, qz = bz - az;
        float nx = fmaf(qy, bcz, fmaf(-qz, bcy, 1e-8f));
        float ny = fmaf(qz, bcx, fmaf(-qx, bcz, 1e-8f));
        float nz = fmaf(qx, bcy, fmaf(-qy, bcx, 1e-8f));
        float in_ = frsqrt(fmaf(nx, nx, fmaf(ny, ny, nz * nz)));
        nx *= in_; ny *= in_; nz *= in_;

        float mx = ny * bcz - nz * bcy;
        float my = nz * bcx - nx * bcz;
        float mz = nx * bcy - ny * bcx;

        float ux = fmaf(CA0, bcx, fmaf(r1, mx, r2 * nx));
        float uy = fmaf(CA0, bcy, fmaf(r1, my, r2 * ny));
        float uz = fmaf(CA0, bcz, fmaf(r1, mz, r2 * nz));

        px = fmaf(B0, ux, px);
        py = fmaf(B0, uy, py);
        pz = fmaf(B0, uz, pz);
        rec[0] = px; rec[1] = py; rec[2] = pz;

        float iun = frsqrt(fmaf(ux, ux, fmaf(uy, uy, uz * uz)));
        vx = -bcx; vy = -bcy; vz = -bcz;
        wx = ux * iun; wy = uy * iun; wz = uz * iun;
    } else {
        // canonical entry frame (boundary geometry constant: i0 % 3 == 0)
        px = 0.f; py = 0.f; pz = 0.f;
        wx = 1.f; wy = 0.f; wz = 0.f;
        vx = -CA2; vy = SA2; vz = 0.f;
        STEP(0, CA0, B0, IS2);
    }
    STEP( 1, CA1, B1, IS0); STEP( 2, CA2, B2, IS1);
    #pragma unroll
    for (int m = 1; m < 7; ++m) {
        STEP(3*m + 0, CA0, B0, IS2);
        STEP(3*m + 1, CA1, B1, IS0);
        STEP(3*m + 2, CA2, B2, IS1);
    }
    #undef STEP

    {   // publish segment exit: last point, final w, final v (local coords)
        float* e9 = &ex[(c * SEG + s) * 9];
        e9[0] = px; e9[1] = py; e9[2] = pz;
        e9[3] = wx; e9[4] = wy; e9[5] = wz;
        e9[6] = vx; e9[7] = vy; e9[8] = vz;
    }
    __syncthreads();

    // ---- phase 2: per-chain sequential compose (16 lanes, 5 iters) ----
    if (tid < CHAINS) {
        const int cc = tid;
        float* r0 = &rp[cc * SEG * 12];
        r0[0] = 1.f; r0[1] = 0.f; r0[2] = 0.f;
        r0[3] = 0.f; r0[4] = 1.f; r0[5] = 0.f;
        r0[6] = 0.f; r0[7] = 0.f; r0[8] = 1.f;
        r0[9] = 0.f; r0[10] = 0.f; r0[11] = 0.f;

        const float* e0 = &ex[cc * SEG * 9];
        float pex = e0[0], pey = e0[1], pez = e0[2];
        float wex = e0[3], wey = e0[4], wez = e0[5];
        float vex = e0[6], vey = e0[7], vez = e0[8];

        #pragma unroll
        for (int ss = 1; ss < SEG; ++ss) {
            // Gram-Schmidt basis from entry (w, v)
            float d  = fmaf(vex, wex, fmaf(vey, wey, vez * wez));
            float tx = fmaf(-d, wex, vex);
            float ty = fmaf(-d, wey, vey);
            float tz = fmaf(-d, wez, vez);
            float it = frsqrt(fmaf(tx, tx, fmaf(ty, ty, fmaf(tz, tz, 1e-20f))));
            float g1x = wex,     g1y = wey,     g1z = wez;
            float g2x = tx * it, g2y = ty * it, g2z = tz * it;
            float g3x = g1y * g2z - g1z * g2y;
            float g3y = g1z * g2x - g1x * g2z;
            float g3z = g1x * g2y - g1y * g2x;

            float* rr = &rp[(cc * SEG + ss) * 12];
            rr[0] = g1x; rr[1] = g1y; rr[2] = g1z;
            rr[3] = g2x; rr[4] = g2y; rr[5] = g2z;
            rr[6] = g3x; rr[7] = g3y; rr[8] = g3z;
            rr[9] = pex; rr[10] = pey; rr[11] = pez;

            // chain exit -> next entry (global coords)
            const float* es = &ex[(cc * SEG + ss) * 9];
            float qx = es[0], qy = es[1], qz = es[2];
            float wfx = es[3], wfy = es[4], wfz = es[5];
            float vfx = es[6], vfy = es[7], vfz = es[8];

            float npx = pex + qx * g1x + qy * g2x + qz * g3x;
            float npy = pey + qx * g1y + qy * g2y + qz * g3y;
            float npz = pez + qx * g1z + qy * g2z + qz * g3z;
            wex = wfx * g1x + wfy * g2x + wfz * g3x;
            wey = wfx * g1y + wfy * g2y + wfz * g3y;
            wez = wfx * g1z + wfy * g2z + wfz * g3z;
            vex = vfx * g1x + vfy * g2x + vfz * g3x;
            vey = vfx * g1y + vfy * g2y + vfz * g3y;
            vez = vfx * g1z + vfy * g2z + vfz * g3z;
            pex = npx; pey = npy; pez = npz;
        }
    }
    __syncthreads();

    // ---- phase 3: per-thread transform of own records (R in registers) ----
    {
        const float* rr = &rp[(c * SEG + s) * 12];
        float g1x = rr[0], g1y = rr[1], g1z = rr[2];
        float g2x = rr[3], g2y = rr[4], g2z = rr[5];
        float g3x = rr[6], g3y = rr[7], g3z = rr[8];
        float ppx = rr[9], ppy = rr[10], ppz = rr[11];
        #pragma unroll 3
        for (int j = 0; j < LSEG; ++j) {
            float qx = rec[j * 3 + 0];
            float qy = rec[j * 3 + 1];
            float qz = rec[j * 3 + 2];
            rec[j * 3 + 0] = fmaf(qx, g1x, fmaf(qy, g2x, fmaf(qz, g3x, ppx)));
            rec[j * 3 + 1] = fmaf(qx, g1y, fmaf(qy, g2y, fmaf(qz, g3y, ppy)));
            rec[j * 3 + 2] = fmaf(qx, g1z, fmaf(qy, g2z, fmaf(qz, g3z, ppz)));
        }
    }
    __syncthreads();

    // ---- phase 4: flat float4 copy (buf layout == global layout) ----
    {
        const float4* src = (const float4*)buf;
        float4*       dst = (float4*)(out + (size_t)Bbase * (NRES * 3));
        #pragma unroll
        for (int i = 0; i < 15; ++i)             // 15 * 96 = 1440 of 1512
            dst[tid + i * TPB] = src[tid + i * TPB];
        if (tid < 72)
            dst[tid + 1440] = src[tid + 1440];
    }
}

extern "C" void kernel_launch(void* const* d_in, const int* in_sizes, int n_in,
                              void* d_out, int out_size)
{
    const float* angles = (const float*)d_in[0];   // (B, 252) f32
    const float* prev   = (const float*)d_in[1];   // (B, 3, 3) f32
    float*       out    = (float*)d_out;           // (B, 126, 3) f32

    const int B = in_sizes[0] / (2 * NRES);        // 65536
    dihedral_kernel<<<B / CHAINS, TPB>>>(angles, prev, out);
}